// round 6
// baseline (speedup 1.0000x reference)
#include <cuda_runtime.h>
#include <cuda_bf16.h>

#define SS     256
#define BB     64
#define INF    256
#define HH     256
#define INNER  512
#define AA     64
#define LEVELS 7
#define NB     144
#define NT     256

// ------------------- device scratch -------------------
__device__ float g_xv[2][SS * BB * HH];
__device__ float g_px[SS * BB * INNER];
__device__ float g_pa[SS * BB * AA];
__device__ float g_xm[2][SS * BB];
__device__ float g_phv[2][SS * BB];
__device__ float g_tmp[BB * INNER];
__device__ float g_h[2][BB * HH];
__device__ float g_hv[BB];
__device__ float g_both[BB], g_xonly[BB], g_honly[BB];

// ------------------- slot-based grid barrier -------------------
__device__ volatile unsigned g_arrive[NB];
__device__ volatile unsigned g_gen = 0;

__device__ __forceinline__ void gbar(unsigned ep) {
    __syncthreads();
    if (blockIdx.x == 0) {
        int tid = threadIdx.x;
        if (tid >= 1 && tid < NB) {
            while (g_arrive[tid] < ep) { }
        }
        __syncthreads();
        if (tid == 0) { __threadfence(); g_gen = ep; }
        __syncthreads();
    } else {
        if (threadIdx.x == 0) {
            __threadfence();
            g_arrive[blockIdx.x] = ep;
            while (g_gen < ep) { }
            __threadfence();   // acquire before block proceeds
        }
        __syncthreads();
    }
}

__device__ __forceinline__ float lrelu(float z) { return z >= 0.f ? z : 0.01f * z; }

__device__ __forceinline__ void fma4(float4& acc, float s, const float4& v) {
    acc.x = fmaf(s, v.x, acc.x);
    acc.y = fmaf(s, v.y, acc.y);
    acc.z = fmaf(s, v.z, acc.z);
    acc.w = fmaf(s, v.w, acc.w);
}

__device__ __forceinline__ void red4(float4& a, int m) {
    a.x += __shfl_xor_sync(0xffffffffu, a.x, m);
    a.y += __shfl_xor_sync(0xffffffffu, a.y, m);
    a.z += __shfl_xor_sync(0xffffffffu, a.z, m);
    a.w += __shfl_xor_sync(0xffffffffu, a.w, m);
}

// K=256 outer-product dot: 4 output columns (at wp), activations xr[0..255] in smem.
// Weight row stride NSTR; lanes across a warp read consecutive columns -> coalesced.
template<int NSTR>
__device__ __forceinline__ float4 dotrow256(const float* __restrict__ wp,
                                            const float* __restrict__ xr) {
    float4 acc = {0.f, 0.f, 0.f, 0.f};
    #pragma unroll 4
    for (int k = 0; k < 256; k += 4) {
        float4 hx = *(const float4*)&xr[k];
        const float* wk = wp + (size_t)k * NSTR;
        float4 w0 = *(const float4*)&wk[0];
        float4 w1 = *(const float4*)&wk[NSTR];
        float4 w2 = *(const float4*)&wk[2 * NSTR];
        float4 w3 = *(const float4*)&wk[3 * NSTR];
        fma4(acc, hx.x, w0); fma4(acc, hx.y, w1);
        fma4(acc, hx.z, w2); fma4(acc, hx.w, w3);
    }
    return acc;
}

// ------------------- persistent kernel -------------------
__global__ void __launch_bounds__(NT)
enc_kernel(const float* __restrict__ x, const float* __restrict__ mask,
           const float* __restrict__ W_emb, const float* __restrict__ b_emb,
           const float* __restrict__ W, const float* __restrict__ U, const float* __restrict__ b,
           const float* __restrict__ W1, const float* __restrict__ b1,
           const float* __restrict__ Wa1, const float* __restrict__ Ua1, const float* __restrict__ ba1,
           const float* __restrict__ Wa3, const float* __restrict__ ba3,
           float* __restrict__ out)
{
    __shared__ float sm[4160];
    const int tid = threadIdx.x;
    const int bid = blockIdx.x;
    unsigned ep = g_gen;   // persisted epoch base (replay-safe)

    // ---------------- init masks ----------------
    for (int idx = bid * NT + tid; idx < SS * BB; idx += NB * NT) {
        int t = idx / BB, i = idx % BB;
        float m = mask[i * SS + t];
        g_xm[0][idx] = m;
        g_phv[0][idx] = m;
    }
    gbar(++ep);

    // ---------------- Phase E: xe = x @ W_emb + b_emb  (time-major rows m = t*B+i) ----------------
    for (int tile = bid; tile < 4096; tile += NB) {
        int mt = tile >> 2, cg = tile & 3;
        int rbase = mt * 16, cbase = cg * 64;
        for (int u = tid; u < 16 * 64; u += NT) {
            int r = u >> 6, off = (u & 63) * 4;
            int m = rbase + r;
            int i = m & (BB - 1), t = m >> 6;
            *(float4*)&sm[r * INF + off] = *(const float4*)&x[(i * SS + t) * INF + off];
        }
        __syncthreads();
        int r = tid >> 4, q = tid & 15;
        int col = cbase + q * 4;
        float4 acc = dotrow256<HH>(W_emb + col, &sm[r * INF]);
        float4 bv = *(const float4*)&b_emb[col];
        acc.x += bv.x; acc.y += bv.y; acc.z += bv.z; acc.w += bv.w;
        *(float4*)&g_xv[0][(rbase + r) * HH + col] = acc;
        __syncthreads();
    }
    gbar(++ep);

    // ---------------- levels ----------------
    for (int lvl = 0; lvl < LEVELS; lvl++) {
        const int cur = lvl & 1, nxt = cur ^ 1;
        const float* xv = g_xv[cur];

        // ---- Phase P: PX = xv@W + b  (8192 tiles) ; PA = xv@Wa1 + ba1 (1024 tiles) ----
        for (int tile = bid; tile < 9216; tile += NB) {
            bool is_px = (tile < 8192);
            int rbase, cbase;
            if (is_px) { rbase = (tile >> 3) * 16; cbase = (tile & 7) * 64; }
            else       { rbase = (tile - 8192) * 16; cbase = 0; }
            for (int u = tid; u < 16 * 64; u += NT) {
                int r = u >> 6, off = (u & 63) * 4;
                *(float4*)&sm[r * HH + off] = *(const float4*)&xv[(rbase + r) * HH + off];
            }
            __syncthreads();
            int r = tid >> 4, q = tid & 15;
            if (is_px) {
                int col = cbase + q * 4;
                float4 acc = dotrow256<INNER>(W + col, &sm[r * HH]);
                float4 bv = *(const float4*)&b[col];
                acc.x += bv.x; acc.y += bv.y; acc.z += bv.z; acc.w += bv.w;
                *(float4*)&g_px[(rbase + r) * INNER + col] = acc;
            } else {
                int col = q * 4;
                float4 acc = dotrow256<AA>(Wa1 + col, &sm[r * HH]);
                float4 bv = *(const float4*)&ba1[col];
                acc.x += bv.x; acc.y += bv.y; acc.z += bv.z; acc.w += bv.w;
                *(float4*)&g_pa[(rbase + r) * AA + col] = acc;
            }
            __syncthreads();
        }
        // per-level state init
        if (bid == NB - 1) {
            for (int idx = tid; idx < BB * HH; idx += NT) g_h[0][idx] = 0.f;
            if (tid < BB) {
                g_hv[tid] = 0.f;
                g_xm[nxt][(SS - 1) * BB + tid] = 1.f;
            }
        }
        gbar(++ep);

        // ---- Phase S: 256 sequential steps ----
        for (int t = 0; t < SS; t++) {
            const float* hcur = g_h[t & 1];
            float* hnext = g_h[(t + 1) & 1];

            // ======== stage A ========
            if (bid < 128) {
                // tmp[64,512]: block = (sg: 8 samples) x (cg: 32 cols). 4-way K-split in warp.
                int rbase = (bid & 7) * 8, cbase = (bid >> 3) * 32;
                for (int u = tid; u < 8 * 64; u += NT) {
                    int r = u >> 6, off = (u & 63) * 4;
                    *(float4*)&sm[r * HH + off] = *(const float4*)&hcur[(rbase + r) * HH + off];
                }
                __syncthreads();
                int r = tid >> 5, lane = tid & 31;
                int ks = lane >> 3, q = lane & 7;          // ks in [0,4), q in [0,8)
                const float* up = U + cbase + q * 4;       // row stride INNER
                const float* hr = &sm[r * HH + ks * 64];
                float4 acc = {0.f, 0.f, 0.f, 0.f};
                #pragma unroll 4
                for (int kk = 0; kk < 64; kk += 4) {
                    float4 hx = *(const float4*)&hr[kk];
                    const float* uk = up + (size_t)(ks * 64 + kk) * INNER;
                    float4 w0 = *(const float4*)&uk[0];
                    float4 w1 = *(const float4*)&uk[INNER];
                    float4 w2 = *(const float4*)&uk[2 * INNER];
                    float4 w3 = *(const float4*)&uk[3 * INNER];
                    fma4(acc, hx.x, w0); fma4(acc, hx.y, w1);
                    fma4(acc, hx.z, w2); fma4(acc, hx.w, w3);
                }
                red4(acc, 8); red4(acc, 16);
                if (ks == 0) {
                    int i = rbase + r, col = cbase + q * 4;
                    float4 pxv = *(const float4*)&g_px[(t * BB + i) * INNER + col];
                    float4 o;
                    o.x = lrelu(acc.x + pxv.x); o.y = lrelu(acc.y + pxv.y);
                    o.z = lrelu(acc.z + pxv.z); o.w = lrelu(acc.w + pxv.w);
                    *(float4*)&g_tmp[i * INNER + col] = o;
                }
            } else {
                // ---- action gate: 16 blocks x 4 samples ----
                int rbase = (bid - 128) * 4;
                float* as = sm + 2048;                      // partials area
                for (int u = tid; u < 4 * 64; u += NT) {
                    int r = u >> 6, off = (u & 63) * 4;
                    *(float4*)&sm[r * HH + off] = *(const float4*)&hcur[(rbase + r) * HH + off];
                }
                __syncthreads();
                {
                    int w = tid >> 5, lane = tid & 31;
                    int r = w >> 1, kh = w & 1;             // 4 samples x 2 K-halves
                    int ks = lane >> 4, j4 = lane & 15;     // 2-way K-split x 16 col-quads
                    const float* up = Ua1 + j4 * 4;         // row stride AA
                    const float* hr = &sm[r * HH + kh * 128 + ks * 64];
                    float4 acc = {0.f, 0.f, 0.f, 0.f};
                    #pragma unroll 4
                    for (int kk = 0; kk < 64; kk += 4) {
                        float4 hx = *(const float4*)&hr[kk];
                        const float* uk = up + (size_t)(kh * 128 + ks * 64 + kk) * AA;
                        float4 w0 = *(const float4*)&uk[0];
                        float4 w1 = *(const float4*)&uk[AA];
                        float4 w2 = *(const float4*)&uk[2 * AA];
                        float4 w3 = *(const float4*)&uk[3 * AA];
                        fma4(acc, hx.x, w0); fma4(acc, hx.y, w1);
                        fma4(acc, hx.z, w2); fma4(acc, hx.w, w3);
                    }
                    red4(acc, 16);
                    if (ks == 0)
                        *(float4*)&as[((r * 2 + kh) * 16 + j4) * 4] = acc;
                }
                __syncthreads();
                {
                    int w = tid >> 5, lane = tid & 31;
                    if (w < 4) {
                        int i = rbase + w;
                        float p = 0.f;
                        if (lane < 16) {
                            float4 p0 = *(const float4*)&as[((w * 2 + 0) * 16 + lane) * 4];
                            float4 p1 = *(const float4*)&as[((w * 2 + 1) * 16 + lane) * 4];
                            float4 pav = *(const float4*)&g_pa[(t * BB + i) * AA + lane * 4];
                            float a0 = lrelu(p0.x + p1.x + pav.x);
                            float a1 = lrelu(p0.y + p1.y + pav.y);
                            float a2 = lrelu(p0.z + p1.z + pav.z);
                            float a3 = lrelu(p0.w + p1.w + pav.w);
                            float4 w3v = *(const float4*)&Wa3[lane * 4];
                            p = a0 * w3v.x + a1 * w3v.y + a2 * w3v.z + a3 * w3v.w;
                        }
                        #pragma unroll
                        for (int o = 16; o; o >>= 1) p += __shfl_xor_sync(0xffffffffu, p, o);
                        if (lane == 0) {
                            float s   = 0.2f * (p + ba3[0]) + 0.5f;
                            float nmr = fminf(fmaxf(s, 0.f), 1.f);
                            float lv  = (t == SS - 1) ? 1.f : 0.f;
                            float pm  = g_xm[cur][t * BB + i];
                            float ph  = g_phv[cur][t * BB + i];
                            float hvp = g_hv[i];
                            float nm   = (1.f - lv) * (pm * ph * nmr);
                            float both = pm * ph * (1.f - nm) * hvp;
                            float xo   = pm * ph * (nm + (1.f - nm) * (1.f - hvp));
                            float ho   = (1.f - pm + pm * (1.f - ph)) * (1.f - nm) * hvp;
                            float hv   = both + xo + ho;
                            g_both[i] = both; g_xonly[i] = xo; g_honly[i] = ho;
                            g_hv[i] = hv;
                            g_phv[nxt][t * BB + i] = hv;
                            if (t > 0) g_xm[nxt][(t - 1) * BB + i] = nm;
                        }
                    }
                }
            }
            gbar(++ep);

            // ======== stage B ========
            if (bid < 128) {
                // h[64,256]: block = (sg: 8 samples) x (cg: 16 cols). 8-way K-split in warp.
                int rbase = (bid & 7) * 8, cbase = (bid >> 3) * 16;
                for (int u = tid; u < 8 * 128; u += NT) {
                    int r = u >> 7, off = (u & 127) * 4;
                    *(float4*)&sm[r * INNER + off] = *(const float4*)&g_tmp[(rbase + r) * INNER + off];
                }
                __syncthreads();
                int r = tid >> 5, lane = tid & 31;
                int ks = lane >> 2, q = lane & 3;           // ks in [0,8), q in [0,4)
                const float* wp = W1 + cbase + q * 4;       // row stride HH
                const float* tr = &sm[r * INNER];
                float4 acc = {0.f, 0.f, 0.f, 0.f};
                #pragma unroll 4
                for (int kk = 0; kk < 512; kk += 32) {
                    int k = kk + ks * 4;
                    float4 tx = *(const float4*)&tr[k];
                    const float* wk = wp + (size_t)k * HH;
                    float4 w0 = *(const float4*)&wk[0];
                    float4 w1 = *(const float4*)&wk[HH];
                    float4 w2 = *(const float4*)&wk[2 * HH];
                    float4 w3 = *(const float4*)&wk[3 * HH];
                    fma4(acc, tx.x, w0); fma4(acc, tx.y, w1);
                    fma4(acc, tx.z, w2); fma4(acc, tx.w, w3);
                }
                red4(acc, 4); red4(acc, 8); red4(acc, 16);
                if (ks == 0) {
                    int i = rbase + r, col = cbase + q * 4;
                    float4 b1v = *(const float4*)&b1[col];
                    float h0 = lrelu(acc.x + b1v.x);
                    float h1 = lrelu(acc.y + b1v.y);
                    float h2 = lrelu(acc.z + b1v.z);
                    float h3 = lrelu(acc.w + b1v.w);
                    float bo = g_both[i], xo = g_xonly[i], ho = g_honly[i];
                    float4 xt4  = *(const float4*)&xv[(t * BB + i) * HH + col];
                    float4 hol4 = *(const float4*)&hcur[i * HH + col];
                    float4 hn;
                    hn.x = bo * h0 + xo * xt4.x + ho * hol4.x;
                    hn.y = bo * h1 + xo * xt4.y + ho * hol4.y;
                    hn.z = bo * h2 + xo * xt4.z + ho * hol4.z;
                    hn.w = bo * h3 + xo * xt4.w + ho * hol4.w;
                    *(float4*)&hnext[i * HH + col] = hn;
                    *(float4*)&g_xv[nxt][(t * BB + i) * HH + col] = hn;
                    if (lvl == LEVELS - 1 && t == SS - 1)
                        *(float4*)&out[i * HH + col] = hn;
                }
            }
            gbar(++ep);
        }
    }
}

// ------------------- launcher -------------------
extern "C" void kernel_launch(void* const* d_in, const int* in_sizes, int n_in,
                              void* d_out, int out_size) {
    const float* x     = (const float*)d_in[0];
    const float* mask  = (const float*)d_in[1];
    const float* W_emb = (const float*)d_in[3];
    const float* b_emb = (const float*)d_in[4];
    const float* W     = (const float*)d_in[5];
    const float* U     = (const float*)d_in[6];
    const float* b     = (const float*)d_in[7];
    const float* W1    = (const float*)d_in[8];
    const float* b1    = (const float*)d_in[9];
    const float* Wa1   = (const float*)d_in[10];
    const float* Ua1   = (const float*)d_in[11];
    const float* ba1   = (const float*)d_in[12];
    const float* Wa3   = (const float*)d_in[13];
    const float* ba3   = (const float*)d_in[14];
    float* out = (float*)d_out;

    enc_kernel<<<NB, NT>>>(x, mask, W_emb, b_emb, W, U, b, W1, b1,
                           Wa1, Ua1, ba1, Wa3, ba3, out);
}

// round 7
// speedup vs baseline: 1.5857x; 1.5857x over previous
#include <cuda_runtime.h>
#include <cuda_bf16.h>

#define SS     256
#define BB     64
#define INF    256
#define HH     256
#define INNER  512
#define AA     64
#define LEVELS 7
#define NB     144
#define NT     256

// dynamic smem layout (floats):
//   [0, 8192)       wA  : stage-A U slice   [256 k][32 c]   (bid<128)
//   [0, 16384)      wAct: action Ua1 full   [256 k][64 c]   (bid>=128)
//   [8192, 24576)   wB  : stage-B W1 slice  [512 k][32 c]   (bid<128)
//   [24576, 32768)  work: phase tiles (32x256) / step scratch
#define OFF_WB     8192
#define OFF_WORK   24576
#define SMEM_FLOATS 32768
#define SMEM_BYTES  (SMEM_FLOATS * 4)

// ------------------- device scratch -------------------
__device__ float g_xv[2][SS * BB * HH];
__device__ float g_px[SS * BB * INNER];
__device__ float g_pa[SS * BB * AA];
__device__ float g_xm[2][SS * BB];
__device__ float g_phv[2][SS * BB];
__device__ float g_tmp[BB * INNER];
__device__ float g_h[2][BB * HH];
__device__ float g_hv[BB];
__device__ float g_both[BB], g_xonly[BB], g_honly[BB];

// ------------------- slot-based grid barrier -------------------
__device__ volatile unsigned g_arrive[NB];
__device__ volatile unsigned g_gen = 0;

__device__ __forceinline__ void gbar(unsigned ep) {
    __syncthreads();
    if (blockIdx.x == 0) {
        int tid = threadIdx.x;
        if (tid >= 1 && tid < NB) {
            while (g_arrive[tid] < ep) { }
        }
        __syncthreads();
        if (tid == 0) { __threadfence(); g_gen = ep; }
        __syncthreads();
    } else {
        if (threadIdx.x == 0) {
            __threadfence();                 // release
            g_arrive[blockIdx.x] = ep;
            while (g_gen < ep) { }
            __threadfence();                 // acquire (L1 invalidate; weights are in smem)
        }
        __syncthreads();
    }
}

__device__ __forceinline__ float lrelu(float z) { return z >= 0.f ? z : 0.01f * z; }

__device__ __forceinline__ void fma4(float4& acc, float s, const float4& v) {
    acc.x = fmaf(s, v.x, acc.x);
    acc.y = fmaf(s, v.y, acc.y);
    acc.z = fmaf(s, v.z, acc.z);
    acc.w = fmaf(s, v.w, acc.w);
}

__device__ __forceinline__ float fcomp(const float4& v, int kk) {
    return kk == 0 ? v.x : kk == 1 ? v.y : kk == 2 ? v.z : v.w;
}

__device__ __forceinline__ void red4(float4& a, int m) {
    a.x += __shfl_xor_sync(0xffffffffu, a.x, m);
    a.y += __shfl_xor_sync(0xffffffffu, a.y, m);
    a.z += __shfl_xor_sync(0xffffffffu, a.z, m);
    a.w += __shfl_xor_sync(0xffffffffu, a.w, m);
}

// 4 rows (stride 256 floats in smem) x 4 output cols, K=256, coalesced weight rows.
template<int WSTR>
__device__ __forceinline__ void dot4rows(const float* __restrict__ wp,
                                         const float* __restrict__ xr,
                                         float4& a0, float4& a1, float4& a2, float4& a3) {
    #pragma unroll 2
    for (int k = 0; k < 256; k += 4) {
        float4 h0 = *(const float4*)&xr[k];
        float4 h1 = *(const float4*)&xr[256 + k];
        float4 h2 = *(const float4*)&xr[512 + k];
        float4 h3 = *(const float4*)&xr[768 + k];
        const float* wk = wp + (size_t)k * WSTR;
        float4 w0 = *(const float4*)&wk[0];
        float4 w1 = *(const float4*)&wk[WSTR];
        float4 w2 = *(const float4*)&wk[2 * WSTR];
        float4 w3 = *(const float4*)&wk[3 * WSTR];
        fma4(a0, h0.x, w0); fma4(a1, h1.x, w0); fma4(a2, h2.x, w0); fma4(a3, h3.x, w0);
        fma4(a0, h0.y, w1); fma4(a1, h1.y, w1); fma4(a2, h2.y, w1); fma4(a3, h3.y, w1);
        fma4(a0, h0.z, w2); fma4(a1, h1.z, w2); fma4(a2, h2.z, w2); fma4(a3, h3.z, w2);
        fma4(a0, h0.w, w3); fma4(a1, h1.w, w3); fma4(a2, h2.w, w3); fma4(a3, h3.w, w3);
    }
}

// ------------------- persistent kernel -------------------
__global__ void __launch_bounds__(NT, 1)
enc_kernel(const float* __restrict__ x, const float* __restrict__ mask,
           const float* __restrict__ W_emb, const float* __restrict__ b_emb,
           const float* __restrict__ W, const float* __restrict__ U, const float* __restrict__ b,
           const float* __restrict__ W1, const float* __restrict__ b1,
           const float* __restrict__ Wa1, const float* __restrict__ Ua1, const float* __restrict__ ba1,
           const float* __restrict__ Wa3, const float* __restrict__ ba3,
           float* __restrict__ out)
{
    extern __shared__ float smem[];
    float* const wA   = smem;                 // [256][32]  (bid<128)
    float* const wAct = smem;                 // [256][64]  (bid>=128)
    float* const wB   = smem + OFF_WB;        // [512][32]  (bid<128)
    float* const work = smem + OFF_WORK;      // 8192 floats

    const int tid = threadIdx.x;
    const int bid = blockIdx.x;
    unsigned ep = g_gen;                      // replay-safe epoch base

    // roles
    const int rbaseA = (bid & 7) * 8,  cbaseA = (bid >> 3) * 32;   // stage A (bid<128)
    const int rbaseB = (bid & 15) * 4, cbaseB = (bid >> 4) * 32;   // stage B (bid<128)
    const int rbaseG = (bid - 128) * 4;                            // action  (bid>=128)

    // ---------------- weight staging into smem (once; same weights every level) -------
    if (bid < 128) {
        for (int idx = tid; idx < 256 * 32; idx += NT) {
            int k = idx >> 5, c = idx & 31;
            wA[idx] = U[k * INNER + cbaseA + c];
        }
        for (int idx = tid; idx < 512 * 32; idx += NT) {
            int k = idx >> 5, c = idx & 31;
            wB[idx] = W1[k * HH + cbaseB + c];
        }
    } else {
        for (int idx = tid; idx < 256 * 64; idx += NT) wAct[idx] = Ua1[idx];
    }

    // ---------------- init masks ----------------
    for (int idx = bid * NT + tid; idx < SS * BB; idx += NB * NT) {
        int t = idx / BB, i = idx % BB;
        float m = mask[i * SS + t];
        g_xm[0][idx] = m;
        g_phv[0][idx] = m;
    }
    gbar(++ep);

    // ---------------- Phase E: xe = x @ W_emb + b_emb (tiles of 32 rows x 128 cols) ----
    {
        float* xs = work;
        for (int tile = bid; tile < 1024; tile += NB) {
            int rbase = (tile >> 1) * 32, cbase = (tile & 1) * 128;
            for (int u = tid; u < 2048; u += NT) {
                int r = u >> 6, off = (u & 63) << 2;
                int m = rbase + r;
                int i = m & (BB - 1), t = m >> 6;
                *(float4*)&xs[r * 256 + off] = *(const float4*)&x[(i * SS + t) * INF + off];
            }
            __syncthreads();
            int w = tid >> 5, lane = tid & 31;
            int col = cbase + lane * 4;
            float4 a0 = {0,0,0,0}, a1 = {0,0,0,0}, a2 = {0,0,0,0}, a3 = {0,0,0,0};
            dot4rows<HH>(W_emb + col, &xs[(w * 4) * 256], a0, a1, a2, a3);
            float4 bv = *(const float4*)&b_emb[col];
            a0.x += bv.x; a0.y += bv.y; a0.z += bv.z; a0.w += bv.w;
            a1.x += bv.x; a1.y += bv.y; a1.z += bv.z; a1.w += bv.w;
            a2.x += bv.x; a2.y += bv.y; a2.z += bv.z; a2.w += bv.w;
            a3.x += bv.x; a3.y += bv.y; a3.z += bv.z; a3.w += bv.w;
            int rw = rbase + w * 4;
            *(float4*)&g_xv[0][(rw + 0) * HH + col] = a0;
            *(float4*)&g_xv[0][(rw + 1) * HH + col] = a1;
            *(float4*)&g_xv[0][(rw + 2) * HH + col] = a2;
            *(float4*)&g_xv[0][(rw + 3) * HH + col] = a3;
            __syncthreads();
        }
    }
    gbar(++ep);

    // ---------------- levels ----------------
    for (int lvl = 0; lvl < LEVELS; lvl++) {
        const int cur = lvl & 1, nxt = cur ^ 1;
        const float* xv = g_xv[cur];

        // ---- Phase P: PX (2048 tiles 32x128) + PA (512 tiles 32x64) ----
        {
            float* xs = work;
            for (int tile = bid; tile < 2560; tile += NB) {
                int rbase = (tile < 2048) ? (tile >> 2) * 32 : (tile - 2048) * 32;
                for (int u = tid; u < 2048; u += NT) {
                    int r = u >> 6, off = (u & 63) << 2;
                    *(float4*)&xs[r * 256 + off] = *(const float4*)&xv[(rbase + r) * HH + off];
                }
                __syncthreads();
                if (tile < 2048) {
                    int cbase = (tile & 3) * 128;
                    int w = tid >> 5, lane = tid & 31;
                    int col = cbase + lane * 4;
                    float4 a0 = {0,0,0,0}, a1 = {0,0,0,0}, a2 = {0,0,0,0}, a3 = {0,0,0,0};
                    dot4rows<INNER>(W + col, &xs[(w * 4) * 256], a0, a1, a2, a3);
                    float4 bv = *(const float4*)&b[col];
                    a0.x += bv.x; a0.y += bv.y; a0.z += bv.z; a0.w += bv.w;
                    a1.x += bv.x; a1.y += bv.y; a1.z += bv.z; a1.w += bv.w;
                    a2.x += bv.x; a2.y += bv.y; a2.z += bv.z; a2.w += bv.w;
                    a3.x += bv.x; a3.y += bv.y; a3.z += bv.z; a3.w += bv.w;
                    int rw = rbase + w * 4;
                    *(float4*)&g_px[(rw + 0) * INNER + col] = a0;
                    *(float4*)&g_px[(rw + 1) * INNER + col] = a1;
                    *(float4*)&g_px[(rw + 2) * INNER + col] = a2;
                    *(float4*)&g_px[(rw + 3) * INNER + col] = a3;
                } else {
                    int r = tid >> 4, q = tid & 15;
                    int col = q * 4;
                    const float* xr = &xs[(r * 2) * 256];
                    float4 a0 = {0,0,0,0}, a1 = {0,0,0,0};
                    #pragma unroll 2
                    for (int k = 0; k < 256; k += 4) {
                        float4 h0 = *(const float4*)&xr[k];
                        float4 h1 = *(const float4*)&xr[256 + k];
                        const float* wk = Wa1 + (size_t)k * AA + col;
                        float4 w0 = *(const float4*)&wk[0];
                        float4 w1 = *(const float4*)&wk[AA];
                        float4 w2 = *(const float4*)&wk[2 * AA];
                        float4 w3 = *(const float4*)&wk[3 * AA];
                        fma4(a0, h0.x, w0); fma4(a1, h1.x, w0);
                        fma4(a0, h0.y, w1); fma4(a1, h1.y, w1);
                        fma4(a0, h0.z, w2); fma4(a1, h1.z, w2);
                        fma4(a0, h0.w, w3); fma4(a1, h1.w, w3);
                    }
                    float4 bv = *(const float4*)&ba1[col];
                    a0.x += bv.x; a0.y += bv.y; a0.z += bv.z; a0.w += bv.w;
                    a1.x += bv.x; a1.y += bv.y; a1.z += bv.z; a1.w += bv.w;
                    int rw = rbase + r * 2;
                    *(float4*)&g_pa[(rw + 0) * AA + col] = a0;
                    *(float4*)&g_pa[(rw + 1) * AA + col] = a1;
                }
                __syncthreads();
            }
        }
        // per-level state init
        if (bid == NB - 1) {
            for (int idx = tid; idx < BB * HH; idx += NT) g_h[0][idx] = 0.f;
            if (tid < BB) {
                g_hv[tid] = 0.f;
                g_xm[nxt][(SS - 1) * BB + tid] = 1.f;
            }
        }
        gbar(++ep);

        // ---- Phase S: 256 sequential steps ----
        for (int t = 0; t < SS; t++) {
            const float* hcur = g_h[t & 1];
            float* hnext = g_h[(t + 1) & 1];

            // ======== stage A ========
            if (bid < 128) {
                float* hs  = work;            // [8][256]
                float* psA = work + 2048;     // 8 warps * 260 floats
                for (int u = tid; u < 512; u += NT) {
                    int r = u >> 6, off = (u & 63) << 2;
                    *(float4*)&hs[r * 256 + off] = *(const float4*)&hcur[(rbaseA + r) * HH + off];
                }
                __syncthreads();
                const int w = tid >> 5, lane = tid & 31;
                const int kq = lane >> 3, q = lane & 7;
                const int kbase = w * 32 + kq * 8;
                float4 acc[8];
                #pragma unroll
                for (int s = 0; s < 8; s++) acc[s] = make_float4(0.f, 0.f, 0.f, 0.f);
                #pragma unroll
                for (int ch = 0; ch < 2; ch++) {
                    const int k0 = kbase + ch * 4;
                    float4 hv[8];
                    #pragma unroll
                    for (int s = 0; s < 8; s++) hv[s] = *(const float4*)&hs[s * 256 + k0];
                    #pragma unroll
                    for (int kk = 0; kk < 4; kk++) {
                        float4 wv = *(const float4*)&wA[(k0 + kk) * 32 + q * 4];
                        #pragma unroll
                        for (int s = 0; s < 8; s++) fma4(acc[s], fcomp(hv[s], kk), wv);
                    }
                }
                #pragma unroll
                for (int s = 0; s < 8; s++) { red4(acc[s], 8); red4(acc[s], 16); }
                if (lane < 8) {
                    #pragma unroll
                    for (int s = 0; s < 8; s++)
                        *(float4*)&psA[w * 260 + (s * 8 + q) * 4] = acc[s];
                }
                __syncthreads();
                if (tid < 64) {
                    int s = tid >> 3, q2 = tid & 7;
                    float4 rs = make_float4(0.f, 0.f, 0.f, 0.f);
                    #pragma unroll
                    for (int w2 = 0; w2 < 8; w2++) {
                        float4 p = *(const float4*)&psA[w2 * 260 + (s * 8 + q2) * 4];
                        rs.x += p.x; rs.y += p.y; rs.z += p.z; rs.w += p.w;
                    }
                    int i = rbaseA + s, col = cbaseA + q2 * 4;
                    float4 pxv = *(const float4*)&g_px[(t * BB + i) * INNER + col];
                    float4 o;
                    o.x = lrelu(rs.x + pxv.x); o.y = lrelu(rs.y + pxv.y);
                    o.z = lrelu(rs.z + pxv.z); o.w = lrelu(rs.w + pxv.w);
                    *(float4*)&g_tmp[i * INNER + col] = o;
                }
            } else {
                // ---- action gate: 16 blocks x 4 samples ----
                float* hs = work;             // [4][256]
                float* as = work + 2048;      // 512 floats partials
                for (int u = tid; u < 256; u += NT) {
                    int r = u >> 6, off = (u & 63) << 2;
                    *(float4*)&hs[r * 256 + off] = *(const float4*)&hcur[(rbaseG + r) * HH + off];
                }
                __syncthreads();
                {
                    int w = tid >> 5, lane = tid & 31;
                    int r = w >> 1, kh = w & 1;
                    int ks = lane >> 4, j4 = lane & 15;
                    const float* up = wAct + j4 * 4;
                    const float* hr = &hs[r * 256 + kh * 128 + ks * 64];
                    float4 acc = {0.f, 0.f, 0.f, 0.f};
                    #pragma unroll 4
                    for (int kk = 0; kk < 64; kk += 4) {
                        float4 hx = *(const float4*)&hr[kk];
                        const float* uk = up + (size_t)(kh * 128 + ks * 64 + kk) * AA;
                        float4 w0 = *(const float4*)&uk[0];
                        float4 w1 = *(const float4*)&uk[AA];
                        float4 w2 = *(const float4*)&uk[2 * AA];
                        float4 w3 = *(const float4*)&uk[3 * AA];
                        fma4(acc, hx.x, w0); fma4(acc, hx.y, w1);
                        fma4(acc, hx.z, w2); fma4(acc, hx.w, w3);
                    }
                    red4(acc, 16);
                    if (ks == 0)
                        *(float4*)&as[((r * 2 + kh) * 16 + j4) * 4] = acc;
                }
                __syncthreads();
                {
                    int w = tid >> 5, lane = tid & 31;
                    if (w < 4) {
                        int i = rbaseG + w;
                        float p = 0.f;
                        if (lane < 16) {
                            float4 p0 = *(const float4*)&as[((w * 2 + 0) * 16 + lane) * 4];
                            float4 p1 = *(const float4*)&as[((w * 2 + 1) * 16 + lane) * 4];
                            float4 pav = *(const float4*)&g_pa[(t * BB + i) * AA + lane * 4];
                            float a0 = lrelu(p0.x + p1.x + pav.x);
                            float a1 = lrelu(p0.y + p1.y + pav.y);
                            float a2 = lrelu(p0.z + p1.z + pav.z);
                            float a3 = lrelu(p0.w + p1.w + pav.w);
                            float4 w3v = *(const float4*)&Wa3[lane * 4];
                            p = a0 * w3v.x + a1 * w3v.y + a2 * w3v.z + a3 * w3v.w;
                        }
                        #pragma unroll
                        for (int o = 16; o; o >>= 1) p += __shfl_xor_sync(0xffffffffu, p, o);
                        if (lane == 0) {
                            float s   = 0.2f * (p + ba3[0]) + 0.5f;
                            float nmr = fminf(fmaxf(s, 0.f), 1.f);
                            float lv  = (t == SS - 1) ? 1.f : 0.f;
                            float pm  = g_xm[cur][t * BB + i];
                            float ph  = g_phv[cur][t * BB + i];
                            float hvp = g_hv[i];
                            float nm   = (1.f - lv) * (pm * ph * nmr);
                            float both = pm * ph * (1.f - nm) * hvp;
                            float xo   = pm * ph * (nm + (1.f - nm) * (1.f - hvp));
                            float ho   = (1.f - pm + pm * (1.f - ph)) * (1.f - nm) * hvp;
                            float hv   = both + xo + ho;
                            g_both[i] = both; g_xonly[i] = xo; g_honly[i] = ho;
                            g_hv[i] = hv;
                            g_phv[nxt][t * BB + i] = hv;
                            if (t > 0) g_xm[nxt][(t - 1) * BB + i] = nm;
                        }
                    }
                }
            }
            gbar(++ep);

            // ======== stage B ========
            if (bid < 128) {
                float* ts  = work;            // [4][512]
                float* psB = work + 2048;     // 8 warps * 132 floats
                for (int u = tid; u < 512; u += NT) {
                    int r = u >> 7, off = (u & 127) << 2;
                    *(float4*)&ts[r * 512 + off] = *(const float4*)&g_tmp[(rbaseB + r) * INNER + off];
                }
                __syncthreads();
                const int w = tid >> 5, lane = tid & 31;
                const int kq = lane >> 3, q = lane & 7;
                const int kbase = w * 64 + kq * 16;
                float4 acc[4];
                #pragma unroll
                for (int s = 0; s < 4; s++) acc[s] = make_float4(0.f, 0.f, 0.f, 0.f);
                #pragma unroll
                for (int ch = 0; ch < 4; ch++) {
                    const int k0 = kbase + ch * 4;
                    float4 tv[4];
                    #pragma unroll
                    for (int s = 0; s < 4; s++) tv[s] = *(const float4*)&ts[s * 512 + k0];
                    #pragma unroll
                    for (int kk = 0; kk < 4; kk++) {
                        float4 wv = *(const float4*)&wB[(k0 + kk) * 32 + q * 4];
                        #pragma unroll
                        for (int s = 0; s < 4; s++) fma4(acc[s], fcomp(tv[s], kk), wv);
                    }
                }
                #pragma unroll
                for (int s = 0; s < 4; s++) { red4(acc[s], 8); red4(acc[s], 16); }
                if (lane < 8) {
                    #pragma unroll
                    for (int s = 0; s < 4; s++)
                        *(float4*)&psB[w * 132 + (s * 8 + q) * 4] = acc[s];
                }
                __syncthreads();
                if (tid < 32) {
                    int s = tid >> 3, q2 = tid & 7;
                    float4 rs = make_float4(0.f, 0.f, 0.f, 0.f);
                    #pragma unroll
                    for (int w2 = 0; w2 < 8; w2++) {
                        float4 p = *(const float4*)&psB[w2 * 132 + (s * 8 + q2) * 4];
                        rs.x += p.x; rs.y += p.y; rs.z += p.z; rs.w += p.w;
                    }
                    int i = rbaseB + s, col = cbaseB + q2 * 4;
                    float4 b1v = *(const float4*)&b1[col];
                    float h0 = lrelu(rs.x + b1v.x);
                    float h1 = lrelu(rs.y + b1v.y);
                    float h2 = lrelu(rs.z + b1v.z);
                    float h3 = lrelu(rs.w + b1v.w);
                    float bo = g_both[i], xo = g_xonly[i], ho = g_honly[i];
                    float4 xt4 = *(const float4*)&xv[(t * BB + i) * HH + col];
                    float4 hl4 = *(const float4*)&hcur[i * HH + col];
                    float4 hn;
                    hn.x = bo * h0 + xo * xt4.x + ho * hl4.x;
                    hn.y = bo * h1 + xo * xt4.y + ho * hl4.y;
                    hn.z = bo * h2 + xo * xt4.z + ho * hl4.z;
                    hn.w = bo * h3 + xo * xt4.w + ho * hl4.w;
                    *(float4*)&hnext[i * HH + col] = hn;
                    *(float4*)&g_xv[nxt][(t * BB + i) * HH + col] = hn;
                    if (lvl == LEVELS - 1 && t == SS - 1)
                        *(float4*)&out[i * HH + col] = hn;
                }
            }
            gbar(++ep);
        }
    }
}

// ------------------- launcher -------------------
extern "C" void kernel_launch(void* const* d_in, const int* in_sizes, int n_in,
                              void* d_out, int out_size) {
    const float* x     = (const float*)d_in[0];
    const float* mask  = (const float*)d_in[1];
    const float* W_emb = (const float*)d_in[3];
    const float* b_emb = (const float*)d_in[4];
    const float* W     = (const float*)d_in[5];
    const float* U     = (const float*)d_in[6];
    const float* b     = (const float*)d_in[7];
    const float* W1    = (const float*)d_in[8];
    const float* b1    = (const float*)d_in[9];
    const float* Wa1   = (const float*)d_in[10];
    const float* Ua1   = (const float*)d_in[11];
    const float* ba1   = (const float*)d_in[12];
    const float* Wa3   = (const float*)d_in[13];
    const float* ba3   = (const float*)d_in[14];
    float* out = (float*)d_out;

    cudaFuncSetAttribute(enc_kernel, cudaFuncAttributeMaxDynamicSharedMemorySize, SMEM_BYTES);
    enc_kernel<<<NB, NT, SMEM_BYTES>>>(x, mask, W_emb, b_emb, W, U, b, W1, b1,
                                       Wa1, Ua1, ba1, Wa3, ba3, out);
}

// round 8
// speedup vs baseline: 1.5892x; 1.0022x over previous
#include <cuda_runtime.h>
#include <cuda_bf16.h>

#define SS     256
#define BB     64
#define INF    256
#define HH     256
#define INNER  512
#define AA     64
#define LEVELS 7
#define NB     144
#define NT     256

// dynamic smem layout (floats):
//   [0, 8192)       wA  : stage-A U slice   [256 k][32 c]   (bid<128)
//   [0, 16384)      wAct: action Ua1 full   [256 k][64 c]   (bid>=128)
//   [8192, 24576)   wB  : stage-B W1 slice  [512 k][32 c]   (bid<128)
//   [24576, 32768)  work: phase tiles (32x256) / step scratch
#define OFF_WB     8192
#define OFF_WORK   24576
#define SMEM_FLOATS 32768
#define SMEM_BYTES  (SMEM_FLOATS * 4)

// ------------------- device scratch -------------------
__device__ float g_xv[2][SS * BB * HH];
__device__ float g_px[SS * BB * INNER];
__device__ float g_pa[SS * BB * AA];
__device__ float g_xm[2][SS * BB];
__device__ float g_phv[2][SS * BB];
__device__ float g_tmp[BB * INNER];
__device__ float g_h[2][BB * HH];
__device__ float g_hv[BB];
__device__ float g_both[BB], g_xonly[BB], g_honly[BB];

// ------------------- slot-based grid barrier -------------------
__device__ volatile unsigned g_arrive[NB];
__device__ volatile unsigned g_gen = 0;

__device__ __forceinline__ void gbar(unsigned ep) {
    __syncthreads();
    if (blockIdx.x == 0) {
        int tid = threadIdx.x;
        if (tid >= 1 && tid < NB) {
            while (g_arrive[tid] < ep) { }
        }
        __syncthreads();
        if (tid == 0) { __threadfence(); g_gen = ep; }
        __syncthreads();
    } else {
        if (threadIdx.x == 0) {
            __threadfence();                 // release
            g_arrive[blockIdx.x] = ep;
            while (g_gen < ep) { }
            __threadfence();                 // acquire (L1 invalidate; weights are in smem)
        }
        __syncthreads();
    }
}

__device__ __forceinline__ float lrelu(float z) { return z >= 0.f ? z : 0.01f * z; }

__device__ __forceinline__ void fma4(float4& acc, float s, const float4& v) {
    acc.x = fmaf(s, v.x, acc.x);
    acc.y = fmaf(s, v.y, acc.y);
    acc.z = fmaf(s, v.z, acc.z);
    acc.w = fmaf(s, v.w, acc.w);
}

__device__ __forceinline__ float fcomp(const float4& v, int kk) {
    return kk == 0 ? v.x : kk == 1 ? v.y : kk == 2 ? v.z : v.w;
}

__device__ __forceinline__ void red4(float4& a, int m) {
    a.x += __shfl_xor_sync(0xffffffffu, a.x, m);
    a.y += __shfl_xor_sync(0xffffffffu, a.y, m);
    a.z += __shfl_xor_sync(0xffffffffu, a.z, m);
    a.w += __shfl_xor_sync(0xffffffffu, a.w, m);
}

// 4 rows (stride 256 floats in smem) x 4 output cols, K=256, coalesced weight rows.
template<int WSTR>
__device__ __forceinline__ void dot4rows(const float* __restrict__ wp,
                                         const float* __restrict__ xr,
                                         float4& a0, float4& a1, float4& a2, float4& a3) {
    #pragma unroll 2
    for (int k = 0; k < 256; k += 4) {
        float4 h0 = *(const float4*)&xr[k];
        float4 h1 = *(const float4*)&xr[256 + k];
        float4 h2 = *(const float4*)&xr[512 + k];
        float4 h3 = *(const float4*)&xr[768 + k];
        const float* wk = wp + (size_t)k * WSTR;
        float4 w0 = *(const float4*)&wk[0];
        float4 w1 = *(const float4*)&wk[WSTR];
        float4 w2 = *(const float4*)&wk[2 * WSTR];
        float4 w3 = *(const float4*)&wk[3 * WSTR];
        fma4(a0, h0.x, w0); fma4(a1, h1.x, w0); fma4(a2, h2.x, w0); fma4(a3, h3.x, w0);
        fma4(a0, h0.y, w1); fma4(a1, h1.y, w1); fma4(a2, h2.y, w1); fma4(a3, h3.y, w1);
        fma4(a0, h0.z, w2); fma4(a1, h1.z, w2); fma4(a2, h2.z, w2); fma4(a3, h3.z, w2);
        fma4(a0, h0.w, w3); fma4(a1, h1.w, w3); fma4(a2, h2.w, w3); fma4(a3, h3.w, w3);
    }
}

// ------------------- persistent kernel -------------------
__global__ void __launch_bounds__(NT, 1)
enc_kernel(const float* __restrict__ x, const float* __restrict__ mask,
           const float* __restrict__ W_emb, const float* __restrict__ b_emb,
           const float* __restrict__ W, const float* __restrict__ U, const float* __restrict__ b,
           const float* __restrict__ W1, const float* __restrict__ b1,
           const float* __restrict__ Wa1, const float* __restrict__ Ua1, const float* __restrict__ ba1,
           const float* __restrict__ Wa3, const float* __restrict__ ba3,
           float* __restrict__ out)
{
    extern __shared__ float smem[];
    float* const wA   = smem;                 // [256][32]  (bid<128)
    float* const wAct = smem;                 // [256][64]  (bid>=128)
    float* const wB   = smem + OFF_WB;        // [512][32]  (bid<128)
    float* const work = smem + OFF_WORK;      // 8192 floats

    const int tid = threadIdx.x;
    const int bid = blockIdx.x;
    unsigned ep = g_gen;                      // replay-safe epoch base

    // roles
    const int rbaseA = (bid & 7) * 8,  cbaseA = (bid >> 3) * 32;   // stage A (bid<128)
    const int rbaseB = (bid & 15) * 4, cbaseB = (bid >> 4) * 32;   // stage B (bid<128)
    const int rbaseG = (bid - 128) * 4;                            // action  (bid>=128)

    // ---------------- weight staging into smem (once; same weights every level) -------
    if (bid < 128) {
        for (int idx = tid; idx < 256 * 32; idx += NT) {
            int k = idx >> 5, c = idx & 31;
            wA[idx] = U[k * INNER + cbaseA + c];
        }
        for (int idx = tid; idx < 512 * 32; idx += NT) {
            int k = idx >> 5, c = idx & 31;
            wB[idx] = W1[k * HH + cbaseB + c];
        }
    } else {
        for (int idx = tid; idx < 256 * 64; idx += NT) wAct[idx] = Ua1[idx];
    }

    // ---------------- init masks ----------------
    for (int idx = bid * NT + tid; idx < SS * BB; idx += NB * NT) {
        int t = idx / BB, i = idx % BB;
        float m = mask[i * SS + t];
        g_xm[0][idx] = m;
        g_phv[0][idx] = m;
    }
    gbar(++ep);

    // ---------------- Phase E: xe = x @ W_emb + b_emb (tiles of 32 rows x 128 cols) ----
    {
        float* xs = work;
        for (int tile = bid; tile < 1024; tile += NB) {
            int rbase = (tile >> 1) * 32, cbase = (tile & 1) * 128;
            for (int u = tid; u < 2048; u += NT) {
                int r = u >> 6, off = (u & 63) << 2;
                int m = rbase + r;
                int i = m & (BB - 1), t = m >> 6;
                *(float4*)&xs[r * 256 + off] = *(const float4*)&x[(i * SS + t) * INF + off];
            }
            __syncthreads();
            int w = tid >> 5, lane = tid & 31;
            int col = cbase + lane * 4;
            float4 a0 = {0,0,0,0}, a1 = {0,0,0,0}, a2 = {0,0,0,0}, a3 = {0,0,0,0};
            dot4rows<HH>(W_emb + col, &xs[(w * 4) * 256], a0, a1, a2, a3);
            float4 bv = *(const float4*)&b_emb[col];
            a0.x += bv.x; a0.y += bv.y; a0.z += bv.z; a0.w += bv.w;
            a1.x += bv.x; a1.y += bv.y; a1.z += bv.z; a1.w += bv.w;
            a2.x += bv.x; a2.y += bv.y; a2.z += bv.z; a2.w += bv.w;
            a3.x += bv.x; a3.y += bv.y; a3.z += bv.z; a3.w += bv.w;
            int rw = rbase + w * 4;
            *(float4*)&g_xv[0][(rw + 0) * HH + col] = a0;
            *(float4*)&g_xv[0][(rw + 1) * HH + col] = a1;
            *(float4*)&g_xv[0][(rw + 2) * HH + col] = a2;
            *(float4*)&g_xv[0][(rw + 3) * HH + col] = a3;
            __syncthreads();
        }
    }
    gbar(++ep);

    // ---------------- levels ----------------
    for (int lvl = 0; lvl < LEVELS; lvl++) {
        const int cur = lvl & 1, nxt = cur ^ 1;
        const float* xv = g_xv[cur];

        // ---- Phase P: PX (2048 tiles 32x128) + PA (512 tiles 32x64) ----
        {
            float* xs = work;
            for (int tile = bid; tile < 2560; tile += NB) {
                int rbase = (tile < 2048) ? (tile >> 2) * 32 : (tile - 2048) * 32;
                for (int u = tid; u < 2048; u += NT) {
                    int r = u >> 6, off = (u & 63) << 2;
                    *(float4*)&xs[r * 256 + off] = *(const float4*)&xv[(rbase + r) * HH + off];
                }
                __syncthreads();
                if (tile < 2048) {
                    int cbase = (tile & 3) * 128;
                    int w = tid >> 5, lane = tid & 31;
                    int col = cbase + lane * 4;
                    float4 a0 = {0,0,0,0}, a1 = {0,0,0,0}, a2 = {0,0,0,0}, a3 = {0,0,0,0};
                    dot4rows<INNER>(W + col, &xs[(w * 4) * 256], a0, a1, a2, a3);
                    float4 bv = *(const float4*)&b[col];
                    a0.x += bv.x; a0.y += bv.y; a0.z += bv.z; a0.w += bv.w;
                    a1.x += bv.x; a1.y += bv.y; a1.z += bv.z; a1.w += bv.w;
                    a2.x += bv.x; a2.y += bv.y; a2.z += bv.z; a2.w += bv.w;
                    a3.x += bv.x; a3.y += bv.y; a3.z += bv.z; a3.w += bv.w;
                    int rw = rbase + w * 4;
                    *(float4*)&g_px[(rw + 0) * INNER + col] = a0;
                    *(float4*)&g_px[(rw + 1) * INNER + col] = a1;
                    *(float4*)&g_px[(rw + 2) * INNER + col] = a2;
                    *(float4*)&g_px[(rw + 3) * INNER + col] = a3;
                } else {
                    int r = tid >> 4, q = tid & 15;
                    int col = q * 4;
                    const float* xr = &xs[(r * 2) * 256];
                    float4 a0 = {0,0,0,0}, a1 = {0,0,0,0};
                    #pragma unroll 2
                    for (int k = 0; k < 256; k += 4) {
                        float4 h0 = *(const float4*)&xr[k];
                        float4 h1 = *(const float4*)&xr[256 + k];
                        const float* wk = Wa1 + (size_t)k * AA + col;
                        float4 w0 = *(const float4*)&wk[0];
                        float4 w1 = *(const float4*)&wk[AA];
                        float4 w2 = *(const float4*)&wk[2 * AA];
                        float4 w3 = *(const float4*)&wk[3 * AA];
                        fma4(a0, h0.x, w0); fma4(a1, h1.x, w0);
                        fma4(a0, h0.y, w1); fma4(a1, h1.y, w1);
                        fma4(a0, h0.z, w2); fma4(a1, h1.z, w2);
                        fma4(a0, h0.w, w3); fma4(a1, h1.w, w3);
                    }
                    float4 bv = *(const float4*)&ba1[col];
                    a0.x += bv.x; a0.y += bv.y; a0.z += bv.z; a0.w += bv.w;
                    a1.x += bv.x; a1.y += bv.y; a1.z += bv.z; a1.w += bv.w;
                    int rw = rbase + r * 2;
                    *(float4*)&g_pa[(rw + 0) * AA + col] = a0;
                    *(float4*)&g_pa[(rw + 1) * AA + col] = a1;
                }
                __syncthreads();
            }
        }
        // per-level state init
        if (bid == NB - 1) {
            for (int idx = tid; idx < BB * HH; idx += NT) g_h[0][idx] = 0.f;
            if (tid < BB) {
                g_hv[tid] = 0.f;
                g_xm[nxt][(SS - 1) * BB + tid] = 1.f;
            }
        }
        gbar(++ep);

        // ---- Phase S: 256 sequential steps ----
        for (int t = 0; t < SS; t++) {
            const float* hcur = g_h[t & 1];
            float* hnext = g_h[(t + 1) & 1];

            // ======== stage A ========
            if (bid < 128) {
                float* hs  = work;            // [8][256]
                float* psA = work + 2048;     // 8 warps * 260 floats
                for (int u = tid; u < 512; u += NT) {
                    int r = u >> 6, off = (u & 63) << 2;
                    *(float4*)&hs[r * 256 + off] = *(const float4*)&hcur[(rbaseA + r) * HH + off];
                }
                __syncthreads();
                const int w = tid >> 5, lane = tid & 31;
                const int kq = lane >> 3, q = lane & 7;
                const int kbase = w * 32 + kq * 8;
                float4 acc[8];
                #pragma unroll
                for (int s = 0; s < 8; s++) acc[s] = make_float4(0.f, 0.f, 0.f, 0.f);
                #pragma unroll
                for (int ch = 0; ch < 2; ch++) {
                    const int k0 = kbase + ch * 4;
                    float4 hv[8];
                    #pragma unroll
                    for (int s = 0; s < 8; s++) hv[s] = *(const float4*)&hs[s * 256 + k0];
                    #pragma unroll
                    for (int kk = 0; kk < 4; kk++) {
                        float4 wv = *(const float4*)&wA[(k0 + kk) * 32 + q * 4];
                        #pragma unroll
                        for (int s = 0; s < 8; s++) fma4(acc[s], fcomp(hv[s], kk), wv);
                    }
                }
                #pragma unroll
                for (int s = 0; s < 8; s++) { red4(acc[s], 8); red4(acc[s], 16); }
                if (lane < 8) {
                    #pragma unroll
                    for (int s = 0; s < 8; s++)
                        *(float4*)&psA[w * 260 + (s * 8 + q) * 4] = acc[s];
                }
                __syncthreads();
                if (tid < 64) {
                    int s = tid >> 3, q2 = tid & 7;
                    float4 rs = make_float4(0.f, 0.f, 0.f, 0.f);
                    #pragma unroll
                    for (int w2 = 0; w2 < 8; w2++) {
                        float4 p = *(const float4*)&psA[w2 * 260 + (s * 8 + q2) * 4];
                        rs.x += p.x; rs.y += p.y; rs.z += p.z; rs.w += p.w;
                    }
                    int i = rbaseA + s, col = cbaseA + q2 * 4;
                    float4 pxv = *(const float4*)&g_px[(t * BB + i) * INNER + col];
                    float4 o;
                    o.x = lrelu(rs.x + pxv.x); o.y = lrelu(rs.y + pxv.y);
                    o.z = lrelu(rs.z + pxv.z); o.w = lrelu(rs.w + pxv.w);
                    *(float4*)&g_tmp[i * INNER + col] = o;
                }
            } else {
                // ---- action gate: 16 blocks x 4 samples ----
                float* hs = work;             // [4][256]
                float* as = work + 2048;      // 512 floats partials
                for (int u = tid; u < 256; u += NT) {
                    int r = u >> 6, off = (u & 63) << 2;
                    *(float4*)&hs[r * 256 + off] = *(const float4*)&hcur[(rbaseG + r) * HH + off];
                }
                __syncthreads();
                {
                    int w = tid >> 5, lane = tid & 31;
                    int r = w >> 1, kh = w & 1;
                    int ks = lane >> 4, j4 = lane & 15;
                    const float* up = wAct + j4 * 4;
                    const float* hr = &hs[r * 256 + kh * 128 + ks * 64];
                    float4 acc = {0.f, 0.f, 0.f, 0.f};
                    #pragma unroll 4
                    for (int kk = 0; kk < 64; kk += 4) {
                        float4 hx = *(const float4*)&hr[kk];
                        const float* uk = up + (size_t)(kh * 128 + ks * 64 + kk) * AA;
                        float4 w0 = *(const float4*)&uk[0];
                        float4 w1 = *(const float4*)&uk[AA];
                        float4 w2 = *(const float4*)&uk[2 * AA];
                        float4 w3 = *(const float4*)&uk[3 * AA];
                        fma4(acc, hx.x, w0); fma4(acc, hx.y, w1);
                        fma4(acc, hx.z, w2); fma4(acc, hx.w, w3);
                    }
                    red4(acc, 16);
                    if (ks == 0)
                        *(float4*)&as[((r * 2 + kh) * 16 + j4) * 4] = acc;
                }
                __syncthreads();
                {
                    int w = tid >> 5, lane = tid & 31;
                    if (w < 4) {
                        int i = rbaseG + w;
                        float p = 0.f;
                        if (lane < 16) {
                            float4 p0 = *(const float4*)&as[((w * 2 + 0) * 16 + lane) * 4];
                            float4 p1 = *(const float4*)&as[((w * 2 + 1) * 16 + lane) * 4];
                            float4 pav = *(const float4*)&g_pa[(t * BB + i) * AA + lane * 4];
                            float a0 = lrelu(p0.x + p1.x + pav.x);
                            float a1 = lrelu(p0.y + p1.y + pav.y);
                            float a2 = lrelu(p0.z + p1.z + pav.z);
                            float a3 = lrelu(p0.w + p1.w + pav.w);
                            float4 w3v = *(const float4*)&Wa3[lane * 4];
                            p = a0 * w3v.x + a1 * w3v.y + a2 * w3v.z + a3 * w3v.w;
                        }
                        #pragma unroll
                        for (int o = 16; o; o >>= 1) p += __shfl_xor_sync(0xffffffffu, p, o);
                        if (lane == 0) {
                            float s   = 0.2f * (p + ba3[0]) + 0.5f;
                            float nmr = fminf(fmaxf(s, 0.f), 1.f);
                            float lv  = (t == SS - 1) ? 1.f : 0.f;
                            float pm  = g_xm[cur][t * BB + i];
                            float ph  = g_phv[cur][t * BB + i];
                            float hvp = g_hv[i];
                            float nm   = (1.f - lv) * (pm * ph * nmr);
                            float both = pm * ph * (1.f - nm) * hvp;
                            float xo   = pm * ph * (nm + (1.f - nm) * (1.f - hvp));
                            float ho   = (1.f - pm + pm * (1.f - ph)) * (1.f - nm) * hvp;
                            float hv   = both + xo + ho;
                            g_both[i] = both; g_xonly[i] = xo; g_honly[i] = ho;
                            g_hv[i] = hv;
                            g_phv[nxt][t * BB + i] = hv;
                            if (t > 0) g_xm[nxt][(t - 1) * BB + i] = nm;
                        }
                    }
                }
            }
            gbar(++ep);

            // ======== stage B ========
            if (bid < 128) {
                float* ts  = work;            // [4][512]
                float* psB = work + 2048;     // 8 warps * 132 floats
                for (int u = tid; u < 512; u += NT) {
                    int r = u >> 7, off = (u & 127) << 2;
                    *(float4*)&ts[r * 512 + off] = *(const float4*)&g_tmp[(rbaseB + r) * INNER + off];
                }
                __syncthreads();
                const int w = tid >> 5, lane = tid & 31;
                const int kq = lane >> 3, q = lane & 7;
                const int kbase = w * 64 + kq * 16;
                float4 acc[4];
                #pragma unroll
                for (int s = 0; s < 4; s++) acc[s] = make_float4(0.f, 0.f, 0.f, 0.f);
                #pragma unroll
                for (int ch = 0; ch < 4; ch++) {
                    const int k0 = kbase + ch * 4;
                    float4 tv[4];
                    #pragma unroll
                    for (int s = 0; s < 4; s++) tv[s] = *(const float4*)&ts[s * 512 + k0];
                    #pragma unroll
                    for (int kk = 0; kk < 4; kk++) {
                        float4 wv = *(const float4*)&wB[(k0 + kk) * 32 + q * 4];
                        #pragma unroll
                        for (int s = 0; s < 4; s++) fma4(acc[s], fcomp(tv[s], kk), wv);
                    }
                }
                #pragma unroll
                for (int s = 0; s < 4; s++) { red4(acc[s], 8); red4(acc[s], 16); }
                if (lane < 8) {
                    #pragma unroll
                    for (int s = 0; s < 4; s++)
                        *(float4*)&psB[w * 132 + (s * 8 + q) * 4] = acc[s];
                }
                __syncthreads();
                if (tid < 32) {
                    int s = tid >> 3, q2 = tid & 7;
                    float4 rs = make_float4(0.f, 0.f, 0.f, 0.f);
                    #pragma unroll
                    for (int w2 = 0; w2 < 8; w2++) {
                        float4 p = *(const float4*)&psB[w2 * 132 + (s * 8 + q2) * 4];
                        rs.x += p.x; rs.y += p.y; rs.z += p.z; rs.w += p.w;
                    }
                    int i = rbaseB + s, col = cbaseB + q2 * 4;
                    float4 b1v = *(const float4*)&b1[col];
                    float h0 = lrelu(rs.x + b1v.x);
                    float h1 = lrelu(rs.y + b1v.y);
                    float h2 = lrelu(rs.z + b1v.z);
                    float h3 = lrelu(rs.w + b1v.w);
                    float bo = g_both[i], xo = g_xonly[i], ho = g_honly[i];
                    float4 xt4 = *(const float4*)&xv[(t * BB + i) * HH + col];
                    float4 hl4 = *(const float4*)&hcur[i * HH + col];
                    float4 hn;
                    hn.x = bo * h0 + xo * xt4.x + ho * hl4.x;
                    hn.y = bo * h1 + xo * xt4.y + ho * hl4.y;
                    hn.z = bo * h2 + xo * xt4.z + ho * hl4.z;
                    hn.w = bo * h3 + xo * xt4.w + ho * hl4.w;
                    *(float4*)&hnext[i * HH + col] = hn;
                    *(float4*)&g_xv[nxt][(t * BB + i) * HH + col] = hn;
                    if (lvl == LEVELS - 1 && t == SS - 1)
                        *(float4*)&out[i * HH + col] = hn;
                }
            }
            gbar(++ep);
        }
    }
}

// ------------------- launcher -------------------
extern "C" void kernel_launch(void* const* d_in, const int* in_sizes, int n_in,
                              void* d_out, int out_size) {
    const float* x     = (const float*)d_in[0];
    const float* mask  = (const float*)d_in[1];
    const float* W_emb = (const float*)d_in[3];
    const float* b_emb = (const float*)d_in[4];
    const float* W     = (const float*)d_in[5];
    const float* U     = (const float*)d_in[6];
    const float* b     = (const float*)d_in[7];
    const float* W1    = (const float*)d_in[8];
    const float* b1    = (const float*)d_in[9];
    const float* Wa1   = (const float*)d_in[10];
    const float* Ua1   = (const float*)d_in[11];
    const float* ba1   = (const float*)d_in[12];
    const float* Wa3   = (const float*)d_in[13];
    const float* ba3   = (const float*)d_in[14];
    float* out = (float*)d_out;

    cudaFuncSetAttribute(enc_kernel, cudaFuncAttributeMaxDynamicSharedMemorySize, SMEM_BYTES);
    enc_kernel<<<NB, NT, SMEM_BYTES>>>(x, mask, W_emb, b_emb, W, U, b, W1, b1,
                                       Wa1, Ua1, ba1, Wa3, ba3, out);
}

// round 9
// speedup vs baseline: 4.0453x; 2.5455x over previous
#include <cuda_runtime.h>

#define SS     256
#define BB     64
#define INF    256
#define HH     256
#define INNER  512
#define AA     64
#define LEVELS 7
#define NB     126
#define NT     256
#define NSUPER (SS + 2 * (LEVELS - 1))   // 268

// smem (floats): wP[512][32] @0 ; wB1[512][16] @16384 ; gates 3*64 @24576 ;
//                swa3[64] @24768 ; sb1[16] @24832 ; sbias1[32] @24848
#define OFF_WB1   16384
#define OFF_SG    24576
#define OFF_WA3   24768
#define OFF_B1    24832
#define OFF_BIAS1 24848
#define SMEM_FLOATS 24896
#define SMEM_BYTES  (SMEM_FLOATS * 4)

__device__ float g_xe[SS * BB * HH];           // embedding, time-major
__device__ float g_dm[SS * BB];
__device__ float g_tmpL[LEVELS][BB * INNER];
__device__ float g_aL[LEVELS][BB * AA];
__device__ float r_xv[LEVELS][4][BB * HH];     // h ring (= next level's xv)
__device__ float r_nm[LEVELS][4][BB];
__device__ float r_hv[LEVELS][4][BB];

__device__ volatile unsigned g_arrive[NB];
__device__ volatile unsigned g_gen = 0;

__device__ __forceinline__ void gbar(unsigned ep) {
    __syncthreads();
    if (blockIdx.x == 0) {
        int tid = threadIdx.x;
        if (tid >= 1 && tid < NB) {
            while (g_arrive[tid] < ep) { }
        }
        __syncthreads();
        if (tid == 0) { __threadfence(); g_gen = ep; }
        __syncthreads();
    } else {
        if (threadIdx.x == 0) {
            __threadfence();
            g_arrive[blockIdx.x] = ep;
            while (g_gen < ep) { }
            __threadfence();
        }
        __syncthreads();
    }
}

__device__ __forceinline__ float lrelu(float z) { return z >= 0.f ? z : 0.01f * z; }

__device__ __forceinline__ void fma4(float4& a, float s, const float4& v) {
    a.x = fmaf(s, v.x, a.x); a.y = fmaf(s, v.y, a.y);
    a.z = fmaf(s, v.z, a.z); a.w = fmaf(s, v.w, a.w);
}
__device__ __forceinline__ float fcomp(const float4& v, int k) {
    return k == 0 ? v.x : k == 1 ? v.y : k == 2 ? v.z : v.w;
}
__device__ __forceinline__ void red4(float4& a, int m) {
    a.x += __shfl_xor_sync(0xffffffffu, a.x, m);
    a.y += __shfl_xor_sync(0xffffffffu, a.y, m);
    a.z += __shfl_xor_sync(0xffffffffu, a.z, m);
    a.w += __shfl_xor_sync(0xffffffffu, a.w, m);
}

// K=256 half: 8 samples (row stride RS, global via __ldg), 32 smem weight cols.
// Thread = (kq in [0,4), q in [0,8)); acc[8] holds 8 samples x 4 cols.
template<long RS>
__device__ __forceinline__ void gemmA_half(const float* __restrict__ src0,
                                           const float* __restrict__ wcol,
                                           int kq, int q, float4 acc[8]) {
    #pragma unroll 4
    for (int j = 0; j < 16; j++) {
        const int k = j * 16 + kq * 4;
        float4 av[8];
        #pragma unroll
        for (int s = 0; s < 8; s++)
            av[s] = __ldg((const float4*)(src0 + (long)s * RS + k));
        #pragma unroll
        for (int kk = 0; kk < 4; kk++) {
            float4 wv = *(const float4*)(wcol + (k + kk) * 32 + q * 4);
            #pragma unroll
            for (int s = 0; s < 8; s++) fma4(acc[s], fcomp(av[s], kk), wv);
        }
    }
}

__global__ void __launch_bounds__(NT, 1)
enc_kernel(const float* __restrict__ x, const float* __restrict__ mask,
           const float* __restrict__ W_emb, const float* __restrict__ b_emb,
           const float* __restrict__ W, const float* __restrict__ U, const float* __restrict__ b,
           const float* __restrict__ W1, const float* __restrict__ b1,
           const float* __restrict__ Wa1, const float* __restrict__ Ua1, const float* __restrict__ ba1,
           const float* __restrict__ Wa3, const float* __restrict__ ba3,
           float* __restrict__ out)
{
    extern __shared__ float smem[];
    float* const wP     = smem;                  // [512][32]
    float* const wB1    = smem + OFF_WB1;        // [512][16]
    float* const sgb    = smem + OFF_SG;
    float* const sgx    = smem + OFF_SG + 64;
    float* const sgh    = smem + OFF_SG + 128;
    float* const swa3   = smem + OFF_WA3;
    float* const sb1    = smem + OFF_B1;
    float* const sbias1 = smem + OFF_BIAS1;

    const int tid = threadIdx.x, bid = blockIdx.x;
    const int w = tid >> 5, lane = tid & 31;
    unsigned ep = g_gen;

    const int lvl1 = bid / 18, cb1 = (bid % 18) * 32;            // phase 1 role
    const bool p2on = bid < 112;
    const int lvl2 = bid >> 4, cb2 = (bid & 15) * 16;            // phase 2 role

    // ---- init dm + ring zero ----
    for (int idx = bid * NT + tid; idx < SS * BB; idx += NB * NT) {
        int t = idx >> 6, i = idx & 63;
        g_dm[idx] = mask[i * SS + t];
    }
    for (int idx = bid * NT + tid; idx < LEVELS * BB * HH; idx += NB * NT)
        r_xv[idx >> 14][3][idx & 16383] = 0.f;
    for (int idx = bid * NT + tid; idx < LEVELS * BB; idx += NB * NT)
        r_hv[idx >> 6][3][idx & 63] = 0.f;

    // ---- embedding: g_xe = x @ W_emb + b_emb (120 blocks: 8 col-slices x 15 t-groups)
    if (bid < 120) {
        const int esl = bid & 7, egr = bid >> 3;
        for (int idx = tid; idx < 256 * 32; idx += NT) {
            int k = idx >> 5, c = idx & 31;
            wP[idx] = W_emb[k * HH + esl * 32 + c];
        }
        __syncthreads();
        const int kq = lane >> 3, q = lane & 7;
        for (int n = egr; n < SS; n += 15) {
            const int ib = 8 * w;
            float4 acc[8];
            #pragma unroll
            for (int s = 0; s < 8; s++) acc[s] = make_float4(0.f, 0.f, 0.f, 0.f);
            gemmA_half<(long)SS * INF>(x + ((long)ib * SS + n) * INF, wP, kq, q, acc);
            #pragma unroll
            for (int s = 0; s < 8; s++) { red4(acc[s], 8); red4(acc[s], 16); }
            if (lane < 8) {
                int col = esl * 32 + lane * 4;
                float4 be = __ldg((const float4*)&b_emb[col]);
                #pragma unroll
                for (int s = 0; s < 8; s++) {
                    float4 o = acc[s];
                    o.x += be.x; o.y += be.y; o.z += be.z; o.w += be.w;
                    *(float4*)&g_xe[((long)n * BB + ib + s) * HH + col] = o;
                }
            }
        }
        __syncthreads();
    }

    // ---- stage persistent weights ----
    for (int idx = tid; idx < 512 * 32; idx += NT) {
        int k = idx >> 5, col = cb1 + (idx & 31);
        float v;
        if (col < 512) v = (k < 256) ? W[k * INNER + col] : U[(k - 256) * INNER + col];
        else { int a = col - 512; v = (k < 256) ? Wa1[k * AA + a] : Ua1[(k - 256) * AA + a]; }
        wP[idx] = v;
    }
    if (p2on) {
        for (int idx = tid; idx < 512 * 16; idx += NT)
            wB1[idx] = W1[(idx >> 4) * HH + cb2 + (idx & 15)];
        if (tid < 16) sb1[tid] = b1[cb2 + tid];
    }
    if (tid < 64) swa3[tid] = Wa3[tid];
    if (tid < 32) {
        int col = cb1 + tid;
        sbias1[tid] = (col < 512) ? b[col] : ba1[col - 512];
    }
    const float ba3v = __ldg(ba3);
    gbar(++ep);

    // ---- wavefront supersteps ----
    for (int u = 0; u < NSUPER; u++) {
        // ======== phase 1: [tmp|a] = lrelu([xt|h] @ [W;U|Wa1;Ua1] + bias) ========
        const int t1 = u - 2 * lvl1;
        if ((unsigned)t1 < SS) {
            const float* xt = (lvl1 == 0) ? &g_xe[(long)t1 * BB * HH]
                                          : r_xv[lvl1 - 1][t1 & 3];
            const float* hp = r_xv[lvl1][(t1 + 3) & 3];
            const int kq = lane >> 3, q = lane & 7, ib = 8 * w;
            float4 acc[8];
            #pragma unroll
            for (int s = 0; s < 8; s++) acc[s] = make_float4(0.f, 0.f, 0.f, 0.f);
            gemmA_half<HH>(xt + (long)ib * HH, wP,            kq, q, acc);
            gemmA_half<HH>(hp + (long)ib * HH, wP + 256 * 32, kq, q, acc);
            #pragma unroll
            for (int s = 0; s < 8; s++) { red4(acc[s], 8); red4(acc[s], 16); }
            if (lane < 8) {
                const int col = cb1 + lane * 4;
                float4 bv = *(const float4*)&sbias1[lane * 4];
                #pragma unroll
                for (int s = 0; s < 8; s++) {
                    int i = ib + s;
                    float4 o;
                    o.x = lrelu(acc[s].x + bv.x); o.y = lrelu(acc[s].y + bv.y);
                    o.z = lrelu(acc[s].z + bv.z); o.w = lrelu(acc[s].w + bv.w);
                    if (col < 512) *(float4*)&g_tmpL[lvl1][i * INNER + col] = o;
                    else           *(float4*)&g_aL[lvl1][i * AA + col - 512] = o;
                }
            }
        }
        gbar(++ep);

        // ======== phase 2: gates + h = g(lrelu(tmp @ W1 + b1), xt, h_old) ========
        const int t2 = u - 2 * lvl2;
        if (p2on && (unsigned)t2 < SS) {
            {   // gate scalars (i = tid>>2, 4-lane dot split)
                int i = tid >> 2, qtr = tid & 3;
                const float* ar = &g_aL[lvl2][i * AA + qtr * 16];
                float p = 0.f;
                #pragma unroll
                for (int c = 0; c < 16; c += 4) {
                    float4 a4 = __ldg((const float4*)&ar[c]);
                    float4 w4 = *(const float4*)&swa3[qtr * 16 + c];
                    p += a4.x * w4.x + a4.y * w4.y + a4.z * w4.z + a4.w * w4.w;
                }
                p += __shfl_xor_sync(0xffffffffu, p, 1);
                p += __shfl_xor_sync(0xffffffffu, p, 2);
                if (qtr == 0) {
                    float sg  = 0.2f * (p + ba3v) + 0.5f;
                    float nmr = fminf(fmaxf(sg, 0.f), 1.f);
                    float lv  = (t2 == SS - 1) ? 1.f : 0.f;
                    float pm, ph;
                    if (lvl2 == 0) { pm = g_dm[t2 * BB + i]; ph = pm; }
                    else {
                        pm = (t2 == SS - 1) ? 1.f : r_nm[lvl2 - 1][(t2 + 1) & 3][i];
                        ph = r_hv[lvl2 - 1][t2 & 3][i];
                    }
                    float hvp = r_hv[lvl2][(t2 + 3) & 3][i];
                    float nm   = (1.f - lv) * (pm * ph * nmr);
                    float both = pm * ph * (1.f - nm) * hvp;
                    float xo   = pm * ph * (nm + (1.f - nm) * (1.f - hvp));
                    float ho   = (1.f - pm + pm * (1.f - ph)) * (1.f - nm) * hvp;
                    sgb[i] = both; sgx[i] = xo; sgh[i] = ho;
                    r_nm[lvl2][t2 & 3][i] = nm;
                    r_hv[lvl2][t2 & 3][i] = both + xo + ho;
                }
            }
            __syncthreads();
            // B GEMM: K=512, 16 cols; thread = (kq in [0,8), q in [0,4)), 8 samples
            const float* tl = g_tmpL[lvl2];
            const int kq = lane >> 2, q = lane & 3, ib = 8 * w;
            float4 acc[8];
            #pragma unroll
            for (int s = 0; s < 8; s++) acc[s] = make_float4(0.f, 0.f, 0.f, 0.f);
            #pragma unroll 4
            for (int j = 0; j < 16; j++) {
                const int k = kq * 64 + j * 4;
                float4 tv[8];
                #pragma unroll
                for (int s = 0; s < 8; s++)
                    tv[s] = __ldg((const float4*)(tl + (long)(ib + s) * INNER + k));
                #pragma unroll
                for (int kk = 0; kk < 4; kk++) {
                    float4 wv = *(const float4*)&wB1[(k + kk) * 16 + q * 4];
                    #pragma unroll
                    for (int s = 0; s < 8; s++) fma4(acc[s], fcomp(tv[s], kk), wv);
                }
            }
            #pragma unroll
            for (int s = 0; s < 8; s++) { red4(acc[s], 4); red4(acc[s], 8); red4(acc[s], 16); }
            if (lane < 4) {
                const int col = cb2 + lane * 4;
                float4 b1v = *(const float4*)&sb1[lane * 4];
                const float* xtp = (lvl2 == 0) ? &g_xe[(long)t2 * BB * HH]
                                               : r_xv[lvl2 - 1][t2 & 3];
                const float* hop = r_xv[lvl2][(t2 + 3) & 3];
                float* hnp = r_xv[lvl2][t2 & 3];
                #pragma unroll
                for (int s = 0; s < 8; s++) {
                    int i = ib + s;
                    float h0 = lrelu(acc[s].x + b1v.x);
                    float h1 = lrelu(acc[s].y + b1v.y);
                    float h2 = lrelu(acc[s].z + b1v.z);
                    float h3 = lrelu(acc[s].w + b1v.w);
                    float bo = sgb[i], xo = sgx[i], ho = sgh[i];
                    float4 xt4 = __ldg((const float4*)&xtp[i * HH + col]);
                    float4 hl4 = __ldg((const float4*)&hop[i * HH + col]);
                    float4 hn;
                    hn.x = bo * h0 + xo * xt4.x + ho * hl4.x;
                    hn.y = bo * h1 + xo * xt4.y + ho * hl4.y;
                    hn.z = bo * h2 + xo * xt4.z + ho * hl4.z;
                    hn.w = bo * h3 + xo * xt4.w + ho * hl4.w;
                    *(float4*)&hnp[i * HH + col] = hn;
                    if (lvl2 == LEVELS - 1 && t2 == SS - 1)
                        *(float4*)&out[i * HH + col] = hn;
                }
            }
        }
        gbar(++ep);
    }
}

extern "C" void kernel_launch(void* const* d_in, const int* in_sizes, int n_in,
                              void* d_out, int out_size) {
    const float* x     = (const float*)d_in[0];
    const float* mask  = (const float*)d_in[1];
    const float* W_emb = (const float*)d_in[3];
    const float* b_emb = (const float*)d_in[4];
    const float* W     = (const float*)d_in[5];
    const float* U     = (const float*)d_in[6];
    const float* b     = (const float*)d_in[7];
    const float* W1    = (const float*)d_in[8];
    const float* b1    = (const float*)d_in[9];
    const float* Wa1   = (const float*)d_in[10];
    const float* Ua1   = (const float*)d_in[11];
    const float* ba1   = (const float*)d_in[12];
    const float* Wa3   = (const float*)d_in[13];
    const float* ba3   = (const float*)d_in[14];
    float* out = (float*)d_out;

    cudaFuncSetAttribute(enc_kernel, cudaFuncAttributeMaxDynamicSharedMemorySize, SMEM_BYTES);
    enc_kernel<<<NB, NT, SMEM_BYTES>>>(x, mask, W_emb, b_emb, W, U, b, W1, b1,
                                       Wa1, Ua1, ba1, Wa3, ba3, out);
}